// round 12
// baseline (speedup 1.0000x reference)
#include <cuda_runtime.h>
#include <cuda_bf16.h>
#include <cstdint>

#define L      2048
#define HOUT   96
#define MTILE  128
#define KC     32
#define NCH    (L / KC)      // 64 chunks
#define NSTAGE 4
#define TPB    512           // 8 consumer warps + 8 producer warps
#define ASTR   40            // bf16 elems per smem row (32 data + 8 pad) = 80B

// stage layout (bytes)
#define AH_O   0             // 128 rows x 80B = 10240
#define AL_O   10240
#define BH_O   20480         //  96 rows x 80B = 7680
#define BL_O   28160
#define STAGE_B 35840
#define SMEM_DYN (NSTAGE * STAGE_B)   // 143360

// ---------------- preprocessed W: transposed + bf16 hi/lo split ----------------
__device__ __align__(16) __nv_bfloat16 g_Wt_h[HOUT * L];   // [n][k]
__device__ __align__(16) __nv_bfloat16 g_Wt_l[HOUT * L];   // [n][k]

__global__ void __launch_bounds__(256)
prep_W_kernel(const float* __restrict__ W)
{
    __shared__ float s[32][97];
    const int k0 = blockIdx.x * 32;
    const int tid = threadIdx.x;
#pragma unroll
    for (int i = 0; i < 12; i++) {
        int idx = tid + i * 256;            // 0..3071
        int k = idx / 96, n = idx % 96;
        s[k][n] = W[(size_t)(k0 + k) * 96 + n];
    }
    __syncthreads();
#pragma unroll
    for (int i = 0; i < 12; i++) {
        int idx = tid + i * 256;
        int n = idx >> 5, k = idx & 31;
        float v = s[k][n];
        __nv_bfloat16 h = __float2bfloat16(v);
        __nv_bfloat16 lo = __float2bfloat16(v - __bfloat162float(h));
        g_Wt_h[(size_t)n * L + k0 + k] = h;
        g_Wt_l[(size_t)n * L + k0 + k] = lo;
    }
}

// ---------------- helpers ----------------
__device__ __forceinline__ void ldsm4(uint32_t* d, uint32_t addr) {
    asm volatile("ldmatrix.sync.aligned.m8n8.x4.shared.b16 {%0,%1,%2,%3}, [%4];"
                 : "=r"(d[0]), "=r"(d[1]), "=r"(d[2]), "=r"(d[3]) : "r"(addr));
}
__device__ __forceinline__ void mma16816(float* c, const uint32_t* a, const uint32_t* b) {
    asm volatile("mma.sync.aligned.m16n8k16.row.col.f32.bf16.bf16.f32 "
                 "{%0,%1,%2,%3}, {%4,%5,%6,%7}, {%8,%9}, {%0,%1,%2,%3};"
                 : "+f"(c[0]), "+f"(c[1]), "+f"(c[2]), "+f"(c[3])
                 : "r"(a[0]), "r"(a[1]), "r"(a[2]), "r"(a[3]), "r"(b[0]), "r"(b[1]));
}
__device__ __forceinline__ void cpasync16(uint32_t dst, const void* src) {
    asm volatile("cp.async.cg.shared.global [%0], [%1], 16;" :: "r"(dst), "l"(src));
}
__device__ __forceinline__ void barsync(int id, int cnt) {
    asm volatile("bar.sync %0, %1;" :: "r"(id), "r"(cnt) : "memory");
}
__device__ __forceinline__ void bararrive(int id, int cnt) {
    asm volatile("bar.arrive %0, %1;" :: "r"(id), "r"(cnt) : "memory");
}
// barrier ids: full[s]=1+s (1..4), empty[s]=5+s (5..8), coeffs=9, producers-only=10

extern "C" __global__ void __launch_bounds__(TPB, 1)
ar2_ws_kernel(const float* __restrict__ x, float* __restrict__ out)
{
    extern __shared__ __align__(128) char smem[];
    __shared__ float st_s1[MTILE], st_s2[MTILE];
    __shared__ float rp_a1[MTILE], rp_a2[MTILE], rp_y1[MTILE],
                     rp_y2[MTILE], rp_lo[MTILE], rp_hi[MTILE];

    const int tid  = threadIdx.x;
    const int lane = tid & 31;
    const int wid  = tid >> 5;
    const int row0 = blockIdx.x * MTILE;
    const uint32_t sbase = (uint32_t)__cvta_generic_to_shared(smem);

    if (wid < 8) {
        // ============ CONSUMERS: 8 warps (2/SMSP), tile 32x48 each ============
        const int wm = wid & 3;           // M group (32 rows)
        const int wn = wid >> 2;          // N group (48 cols)

        float acc[2][6][4];
#pragma unroll
        for (int tm = 0; tm < 2; tm++)
#pragma unroll
            for (int tn = 0; tn < 6; tn++)
#pragma unroll
                for (int q = 0; q < 4; q++) acc[tm][tn][q] = 0.f;

        const uint32_t aBase = sbase
            + (uint32_t)(((wm * 32 + (lane & 15)) * ASTR + ((lane & 16) >> 1)) * 2);
        const uint32_t bBase = sbase
            + (uint32_t)(((wn * 48 + ((lane >> 4) << 3) + (lane & 7)) * ASTR
                          + (lane & 8)) * 2);

        for (int i = 0; i < NCH; i++) {
            const int s = i & 3;
            const uint32_t st = (uint32_t)s * STAGE_B;
            barsync(1 + s, TPB);                       // wait stage filled
#pragma unroll
            for (int ks = 0; ks < 2; ks++) {
                uint32_t aH[2][4], aL[2][4], bH[3][4], bL[3][4];
#pragma unroll
                for (int tm = 0; tm < 2; tm++) {
                    uint32_t off = st + (uint32_t)((tm * 16 * ASTR + ks * 16) * 2);
                    ldsm4(aH[tm], aBase + AH_O + off);
                    ldsm4(aL[tm], aBase + AL_O + off);
                }
#pragma unroll
                for (int np = 0; np < 3; np++) {
                    uint32_t off = st + (uint32_t)((np * 16 * ASTR + ks * 16) * 2);
                    ldsm4(bH[np], bBase + BH_O + off);
                    ldsm4(bL[np], bBase + BL_O + off);
                }
#pragma unroll
                for (int tm = 0; tm < 2; tm++)
#pragma unroll
                    for (int tn = 0; tn < 6; tn++) {
                        const uint32_t* bh = &bH[tn >> 1][(tn & 1) * 2];
                        const uint32_t* bl = &bL[tn >> 1][(tn & 1) * 2];
                        mma16816(acc[tm][tn], aH[tm], bh);   // hi*hi
                        mma16816(acc[tm][tn], aH[tm], bl);   // hi*lo
                        mma16816(acc[tm][tn], aL[tm], bh);   // lo*hi
                    }
            }
            bararrive(5 + s, TPB);                     // stage free
        }

        barsync(9, TPB);                               // coeffs ready

        // ---- epilogue: forecast walk + add GEMM + clip + store ----
        const int cbase = wn * 48 + 2 * (lane & 3);
#pragma unroll
        for (int tm = 0; tm < 2; tm++) {
#pragma unroll
            for (int half = 0; half < 2; half++) {
                const int r = wm * 32 + tm * 16 + (lane >> 2) + half * 8;
                float a1c = rp_a1[r], a2c = rp_a2[r];
                float y1 = rp_y1[r], y2 = rp_y2[r];
                float lo = rp_lo[r], hi = rp_hi[r];
                int h = 0;
                float* op = out + (size_t)(row0 + r) * HOUT;
#pragma unroll
                for (int tn = 0; tn < 6; tn++) {
                    const int target = cbase + tn * 8 + 1;
                    while (h < target) {
                        float yn = fmaf(a1c, y1, a2c * y2);
                        y2 = y1; y1 = yn; h++;
                    }
                    float v0 = y1;
                    { float yn = fmaf(a1c, y1, a2c * y2); y2 = y1; y1 = yn; h++; }
                    float v1 = y1;
                    float o0 = fminf(fmaxf(v0 + acc[tm][tn][half * 2 + 0], lo), hi);
                    float o1 = fminf(fmaxf(v1 + acc[tm][tn][half * 2 + 1], lo), hi);
                    *(float2*)(op + cbase + tn * 8) = make_float2(o0, o1);
                }
            }
        }
    } else {
        // ====== PRODUCERS: 8 warps (2/SMSP) — load + convert + stats + AR2 ======
        const int p  = tid - 256;          // 0..255
        const int g  = p >> 3;             // 0..31 (row group)
        const int c4 = p & 7;              // 0..7 (float4 segment)

        // each thread: rows {32j + g}, j=0..3; double-buffered A registers
        float4 aReg[2][4];
        float s1v[4], s2v[4];
#pragma unroll
        for (int j = 0; j < 4; j++) { s1v[j] = 0.f; s2v[j] = 0.f; }

        // prefetch chunk 0 into buffer 0
#pragma unroll
        for (int j = 0; j < 4; j++)
            aReg[0][j] = *(const float4*)(x + (size_t)(row0 + 32 * j + g) * L + c4 * 4);

        for (int i = 0; i < NCH; i++) {
            const int s   = i & 3;
            const int cur = i & 1;
            if (i >= NSTAGE) barsync(5 + s, TPB);      // wait stage freed
            const uint32_t st = (uint32_t)s * STAGE_B;
            const int k0 = i * KC;

            // ---- B: 768 x 16B cp.async (hi + lo), 3 per thread ----
#pragma unroll
            for (int it = 0; it < 3; it++) {
                int idx = p + it * 256;                // 0..767
                int half = idx >= 384;
                int j2 = idx - half * 384;
                int n = j2 >> 2, c16 = j2 & 3;
                const __nv_bfloat16* src = (half ? g_Wt_l : g_Wt_h)
                                         + (size_t)n * L + k0 + c16 * 8;
                uint32_t dst = sbase + st + (half ? BL_O : BH_O)
                             + (uint32_t)(n * 80 + c16 * 16);
                cpasync16(dst, src);
            }
            asm volatile("cp.async.commit_group;" ::: "memory");

            // ---- EARLY prefetch of chunk i+1 (overlaps convert below) ----
            if (i + 1 < NCH) {
#pragma unroll
                for (int j = 0; j < 4; j++)
                    aReg[cur ^ 1][j] = *(const float4*)(x + (size_t)(row0 + 32 * j + g) * L
                                                        + (i + 1) * KC + c4 * 4);
            }

            // ---- A: convert fp32 -> bf16 hi/lo + STS; fold stats ----
#pragma unroll
            for (int j = 0; j < 4; j++) {
                float4 v = aReg[cur][j];
                s1v[j] += v.x + v.y + v.z + v.w;
                s2v[j] += v.x * v.x + v.y * v.y + v.z * v.z + v.w * v.w;
                __nv_bfloat162 h0 = __float22bfloat162_rn(make_float2(v.x, v.y));
                __nv_bfloat162 h1 = __float22bfloat162_rn(make_float2(v.z, v.w));
                float2 f0 = __bfloat1622float2(h0);
                float2 f1 = __bfloat1622float2(h1);
                __nv_bfloat162 l0 = __float22bfloat162_rn(make_float2(v.x - f0.x, v.y - f0.y));
                __nv_bfloat162 l1 = __float22bfloat162_rn(make_float2(v.z - f1.x, v.w - f1.y));
                uint32_t ob = st + (uint32_t)((32 * j + g) * 80 + c4 * 8);
                *(uint2*)(smem + AH_O + ob) =
                    make_uint2(reinterpret_cast<uint32_t&>(h0), reinterpret_cast<uint32_t&>(h1));
                *(uint2*)(smem + AL_O + ob) =
                    make_uint2(reinterpret_cast<uint32_t&>(l0), reinterpret_cast<uint32_t&>(l1));
            }

            asm volatile("cp.async.wait_group 0;" ::: "memory");
            asm volatile("membar.cta;" ::: "memory");
            bararrive(1 + s, TPB);                     // stage filled
        }

        // drain the last 4 empty signals so stage smem is reusable
        for (int s = 0; s < 4; s++) barsync(5 + s, TPB);

        // ---- stats reduce: 8 threads (c4=0..7) share each row ----
#pragma unroll
        for (int j = 0; j < 4; j++) {
            s1v[j] += __shfl_xor_sync(0xffffffffu, s1v[j], 1);
            s1v[j] += __shfl_xor_sync(0xffffffffu, s1v[j], 2);
            s1v[j] += __shfl_xor_sync(0xffffffffu, s1v[j], 4);
            s2v[j] += __shfl_xor_sync(0xffffffffu, s2v[j], 1);
            s2v[j] += __shfl_xor_sync(0xffffffffu, s2v[j], 2);
            s2v[j] += __shfl_xor_sync(0xffffffffu, s2v[j], 4);
        }
        if (c4 == 0) {
#pragma unroll
            for (int j = 0; j < 4; j++) {
                st_s1[32 * j + g] = s1v[j];
                st_s2[32 * j + g] = s2v[j];
            }
        }
        barsync(10, 256);      // producers-only: stats visible

        // ---- tail staging: last 152 cols of each of 128 rows into stage smem ----
        float* tail = (float*)smem;                    // [128][153]
        for (int idx = p; idx < MTILE * 38; idx += 256) {
            int r = idx / 38, q = (idx % 38) * 4;
            float4 v = *(const float4*)(x + (size_t)(row0 + r) * L + (L - 152) + q);
            float* tp = tail + r * 153;
            tp[q] = v.x; tp[q + 1] = v.y; tp[q + 2] = v.z; tp[q + 3] = v.w;
        }
        barsync(10, 256);      // producers-only: tail visible

        // ---- AR2 fit + std bounds: threads 0..127 handle row p ----
        if (p < 128) {
            const float* y = tail + p * 153 + 2;       // y[0..149] = x[-150:]
            float A11 = 0.f, A22 = 0.f, A12 = 0.f, b1 = 0.f, b2 = 0.f;
            float ym2 = y[0], ym1 = y[1];
#pragma unroll 4
            for (int j = 2; j < 150; j++) {
                float yc = y[j];
                A22 = fmaf(ym2, ym2, A22);
                A11 = fmaf(ym1, ym1, A11);
                A12 = fmaf(ym1, ym2, A12);
                b1  = fmaf(ym1, yc, b1);
                b2  = fmaf(ym2, yc, b2);
                ym2 = ym1; ym1 = yc;
            }
            A11 += 0.001f; A22 += 0.001f;
            float det = A11 * A22 - A12 * A12;
            float inv = 1.0f / det;
            float a1c = (b1 * A22 - b2 * A12) * inv;
            float a2c = (A11 * b2 - A12 * b1) * inv;

            float s1r = st_s1[p], s2r = st_s2[p];
            float mean = s1r * (1.0f / 2048.0f);
            float var  = fmaxf((s2r - s1r * mean) * (1.0f / 2047.0f), 0.f);
            float hstd = fmaxf(sqrtf(var), 1e-6f);
            float last = y[149];

            rp_a1[p] = a1c; rp_a2[p] = a2c;
            rp_y1[p] = y[149]; rp_y2[p] = y[148];
            rp_lo[p] = last - 4.0f * hstd;
            rp_hi[p] = last + 4.0f * hstd;
        }
        asm volatile("membar.cta;" ::: "memory");
        bararrive(9, TPB);     // release consumers into epilogue
    }
}

extern "C" void kernel_launch(void* const* d_in, const int* in_sizes, int n_in,
                              void* d_out, int out_size)
{
    const float* x = (const float*)d_in[0];
    const float* W = (const float*)d_in[1];
    if (n_in >= 2 && in_sizes[0] < in_sizes[1]) {   // defensive: x is the big tensor
        const float* t = x; x = W; W = t;
    }
    float* out = (float*)d_out;

    cudaFuncSetAttribute(ar2_ws_kernel,
                         cudaFuncAttributeMaxDynamicSharedMemorySize, SMEM_DYN);

    prep_W_kernel<<<L / 32, 256>>>(W);                            // 64 blocks
    ar2_ws_kernel<<<(32 * 512) / MTILE, TPB, SMEM_DYN>>>(x, out); // 128 blocks
}

// round 13
// speedup vs baseline: 1.4265x; 1.4265x over previous
#include <cuda_runtime.h>
#include <cuda_bf16.h>
#include <cstdint>

#define L      2048
#define HOUT   96
#define MTILE  128
#define KC     32
#define NCH    (L / KC)      // 64 chunks
#define NSTAGE 4
#define TPB    384           // 8 consumer warps + 4 producer warps
#define ASTR   40            // bf16 elems per smem row (32 data + 8 pad) = 80B

// stage layout (bytes)
#define AF_O   0             // A fp32 staging: 128 rows x 128B = 16384
#define AH_O   16384         // 128 rows x 80B = 10240
#define AL_O   26624
#define BH_O   36864         //  96 rows x 80B = 7680
#define BL_O   44544
#define STAGE_B 52224
#define SMEM_DYN (NSTAGE * STAGE_B)   // 208896

// ---------------- preprocessed W: transposed + bf16 hi/lo split ----------------
__device__ __align__(16) __nv_bfloat16 g_Wt_h[HOUT * L];   // [n][k]
__device__ __align__(16) __nv_bfloat16 g_Wt_l[HOUT * L];   // [n][k]

__global__ void __launch_bounds__(256)
prep_W_kernel(const float* __restrict__ W)
{
    __shared__ float s[32][97];
    const int k0 = blockIdx.x * 32;
    const int tid = threadIdx.x;
#pragma unroll
    for (int i = 0; i < 12; i++) {
        int idx = tid + i * 256;            // 0..3071
        int k = idx / 96, n = idx % 96;
        s[k][n] = W[(size_t)(k0 + k) * 96 + n];
    }
    __syncthreads();
#pragma unroll
    for (int i = 0; i < 12; i++) {
        int idx = tid + i * 256;
        int n = idx >> 5, k = idx & 31;
        float v = s[k][n];
        __nv_bfloat16 h = __float2bfloat16(v);
        __nv_bfloat16 lo = __float2bfloat16(v - __bfloat162float(h));
        g_Wt_h[(size_t)n * L + k0 + k] = h;
        g_Wt_l[(size_t)n * L + k0 + k] = lo;
    }
}

// ---------------- helpers ----------------
__device__ __forceinline__ void ldsm4(uint32_t* d, uint32_t addr) {
    asm volatile("ldmatrix.sync.aligned.m8n8.x4.shared.b16 {%0,%1,%2,%3}, [%4];"
                 : "=r"(d[0]), "=r"(d[1]), "=r"(d[2]), "=r"(d[3]) : "r"(addr));
}
__device__ __forceinline__ void mma16816(float* c, const uint32_t* a, const uint32_t* b) {
    asm volatile("mma.sync.aligned.m16n8k16.row.col.f32.bf16.bf16.f32 "
                 "{%0,%1,%2,%3}, {%4,%5,%6,%7}, {%8,%9}, {%0,%1,%2,%3};"
                 : "+f"(c[0]), "+f"(c[1]), "+f"(c[2]), "+f"(c[3])
                 : "r"(a[0]), "r"(a[1]), "r"(a[2]), "r"(a[3]), "r"(b[0]), "r"(b[1]));
}
__device__ __forceinline__ void cpasync16(uint32_t dst, const void* src) {
    asm volatile("cp.async.cg.shared.global [%0], [%1], 16;" :: "r"(dst), "l"(src));
}
__device__ __forceinline__ void barsync(int id, int cnt) {
    asm volatile("bar.sync %0, %1;" :: "r"(id), "r"(cnt) : "memory");
}
__device__ __forceinline__ void bararrive(int id, int cnt) {
    asm volatile("bar.arrive %0, %1;" :: "r"(id), "r"(cnt) : "memory");
}
// barrier ids: full[s]=1+s (1..4), empty[s]=5+s (5..8), coeffs=9, producers-only=10

extern "C" __global__ void __launch_bounds__(TPB, 1)
ar2_ws_kernel(const float* __restrict__ x, float* __restrict__ out)
{
    extern __shared__ __align__(128) char smem[];
    __shared__ float st_s1[MTILE], st_s2[MTILE];
    __shared__ float rp_a1[MTILE], rp_a2[MTILE], rp_y1[MTILE],
                     rp_y2[MTILE], rp_lo[MTILE], rp_hi[MTILE];

    const int tid  = threadIdx.x;
    const int lane = tid & 31;
    const int wid  = tid >> 5;
    const int row0 = blockIdx.x * MTILE;
    const uint32_t sbase = (uint32_t)__cvta_generic_to_shared(smem);

    if (wid < 8) {
        // ============ CONSUMERS: 8 warps (2/SMSP), tile 32x48 each ============
        const int wm = wid & 3;           // M group (32 rows)
        const int wn = wid >> 2;          // N group (48 cols)

        float acc[2][6][4];
#pragma unroll
        for (int tm = 0; tm < 2; tm++)
#pragma unroll
            for (int tn = 0; tn < 6; tn++)
#pragma unroll
                for (int q = 0; q < 4; q++) acc[tm][tn][q] = 0.f;

        const uint32_t aBase = sbase
            + (uint32_t)(((wm * 32 + (lane & 15)) * ASTR + ((lane & 16) >> 1)) * 2);
        const uint32_t bBase = sbase
            + (uint32_t)(((wn * 48 + ((lane >> 4) << 3) + (lane & 7)) * ASTR
                          + (lane & 8)) * 2);

        for (int i = 0; i < NCH; i++) {
            const int s = i & 3;
            const uint32_t st = (uint32_t)s * STAGE_B;
            barsync(1 + s, TPB);                       // wait stage filled
#pragma unroll
            for (int ks = 0; ks < 2; ks++) {
                uint32_t aH[2][4], aL[2][4], bH[3][4], bL[3][4];
#pragma unroll
                for (int tm = 0; tm < 2; tm++) {
                    uint32_t off = st + (uint32_t)((tm * 16 * ASTR + ks * 16) * 2);
                    ldsm4(aH[tm], aBase + AH_O + off);
                    ldsm4(aL[tm], aBase + AL_O + off);
                }
#pragma unroll
                for (int np = 0; np < 3; np++) {
                    uint32_t off = st + (uint32_t)((np * 16 * ASTR + ks * 16) * 2);
                    ldsm4(bH[np], bBase + BH_O + off);
                    ldsm4(bL[np], bBase + BL_O + off);
                }
#pragma unroll
                for (int tm = 0; tm < 2; tm++)
#pragma unroll
                    for (int tn = 0; tn < 6; tn++) {
                        const uint32_t* bh = &bH[tn >> 1][(tn & 1) * 2];
                        const uint32_t* bl = &bL[tn >> 1][(tn & 1) * 2];
                        mma16816(acc[tm][tn], aH[tm], bh);   // hi*hi
                        mma16816(acc[tm][tn], aH[tm], bl);   // hi*lo
                        mma16816(acc[tm][tn], aL[tm], bh);   // lo*hi
                    }
            }
            bararrive(5 + s, TPB);                     // stage free
        }

        barsync(9, TPB);                               // coeffs ready

        // ---- epilogue: forecast walk + add GEMM + clip + store ----
        const int cbase = wn * 48 + 2 * (lane & 3);
#pragma unroll
        for (int tm = 0; tm < 2; tm++) {
#pragma unroll
            for (int half = 0; half < 2; half++) {
                const int r = wm * 32 + tm * 16 + (lane >> 2) + half * 8;
                float a1c = rp_a1[r], a2c = rp_a2[r];
                float y1 = rp_y1[r], y2 = rp_y2[r];
                float lo = rp_lo[r], hi = rp_hi[r];
                int h = 0;
                float* op = out + (size_t)(row0 + r) * HOUT;
#pragma unroll
                for (int tn = 0; tn < 6; tn++) {
                    const int target = cbase + tn * 8 + 1;
                    while (h < target) {
                        float yn = fmaf(a1c, y1, a2c * y2);
                        y2 = y1; y1 = yn; h++;
                    }
                    float v0 = y1;
                    { float yn = fmaf(a1c, y1, a2c * y2); y2 = y1; y1 = yn; h++; }
                    float v1 = y1;
                    float o0 = fminf(fmaxf(v0 + acc[tm][tn][half * 2 + 0], lo), hi);
                    float o1 = fminf(fmaxf(v1 + acc[tm][tn][half * 2 + 1], lo), hi);
                    *(float2*)(op + cbase + tn * 8) = make_float2(o0, o1);
                }
            }
        }
    } else {
        // ====== PRODUCERS: 4 warps — all-cp.async, lookahead 2 ======
        const int p  = tid - 256;          // 0..127
        const int g  = p >> 3;             // 0..15 (row group)
        const int c4 = p & 7;              // 0..7 (16B segment)

        // issue one chunk's A(fp32)+B(bf16) loads into its stage + commit
        auto issue_group = [&](int j) {
            const uint32_t st = (uint32_t)(j & 3) * STAGE_B;
            const int k0 = j * KC;
            // A fp32: 1024 x 16B -> 8 per thread (thread p covers rows g+16*it)
#pragma unroll
            for (int it = 0; it < 8; it++) {
                int idx = p + it * 128;            // 0..1023
                int row = idx >> 3, seg = idx & 7;
                cpasync16(sbase + st + AF_O + (uint32_t)(row * 128 + seg * 16),
                          x + (size_t)(row0 + row) * L + k0 + seg * 4);
            }
            // B: 768 x 16B (hi + lo) -> 6 per thread
#pragma unroll
            for (int it = 0; it < 6; it++) {
                int idx = p + it * 128;            // 0..767
                int half = idx >= 384;
                int j2 = idx - half * 384;
                int n = j2 >> 2, c16 = j2 & 3;
                cpasync16(sbase + st + (half ? BL_O : BH_O)
                              + (uint32_t)(n * 80 + c16 * 16),
                          (half ? g_Wt_l : g_Wt_h) + (size_t)n * L + k0 + c16 * 8);
            }
            asm volatile("cp.async.commit_group;" ::: "memory");
        };

        float s1v[8], s2v[8];
#pragma unroll
        for (int j = 0; j < 8; j++) { s1v[j] = 0.f; s2v[j] = 0.f; }

        // prologue: groups for chunks 0 and 1 (stages 0,1 initially empty)
        issue_group(0);
        issue_group(1);

        for (int i = 0; i < NCH; i++) {
            const int s = i & 3;
            const uint32_t st = (uint32_t)s * STAGE_B;

            // issue chunk i+2 (lookahead 2)
            const int j = i + 2;
            if (j < NCH) {
                if (j >= NSTAGE) barsync(5 + (j & 3), TPB);   // stage freed?
                issue_group(j);
            }

            // retire chunk i's group (issued ~2 chunk-periods ago)
            if (i < NCH - 2)       asm volatile("cp.async.wait_group 2;" ::: "memory");
            else if (i == NCH - 2) asm volatile("cp.async.wait_group 1;" ::: "memory");
            else                   asm volatile("cp.async.wait_group 0;" ::: "memory");

            // ---- convert A(i): smem fp32 -> bf16 hi/lo + STS; fold stats ----
            // (reads rows this thread itself cp.async'd -> wait_group suffices)
#pragma unroll
            for (int jj = 0; jj < 8; jj++) {
                const int row = 16 * jj + g;
                float4 v = *(const float4*)(smem + st + AF_O + row * 128 + c4 * 16);
                s1v[jj] += v.x + v.y + v.z + v.w;
                s2v[jj] += v.x * v.x + v.y * v.y + v.z * v.z + v.w * v.w;
                __nv_bfloat162 h0 = __float22bfloat162_rn(make_float2(v.x, v.y));
                __nv_bfloat162 h1 = __float22bfloat162_rn(make_float2(v.z, v.w));
                float2 f0 = __bfloat1622float2(h0);
                float2 f1 = __bfloat1622float2(h1);
                __nv_bfloat162 l0 = __float22bfloat162_rn(make_float2(v.x - f0.x, v.y - f0.y));
                __nv_bfloat162 l1 = __float22bfloat162_rn(make_float2(v.z - f1.x, v.w - f1.y));
                uint32_t ob = st + (uint32_t)(row * 80 + c4 * 8);
                *(uint2*)(smem + AH_O + ob) =
                    make_uint2(reinterpret_cast<uint32_t&>(h0), reinterpret_cast<uint32_t&>(h1));
                *(uint2*)(smem + AL_O + ob) =
                    make_uint2(reinterpret_cast<uint32_t&>(l0), reinterpret_cast<uint32_t&>(l1));
            }

            asm volatile("membar.cta;" ::: "memory");
            bararrive(1 + s, TPB);                     // stage filled
        }

        // drain the remaining empty signals so stage smem is reusable
        for (int s = 0; s < 4; s++) barsync(5 + s, TPB);

        // ---- stats reduce: 8 threads (c4=0..7) share each row ----
#pragma unroll
        for (int j = 0; j < 8; j++) {
            s1v[j] += __shfl_xor_sync(0xffffffffu, s1v[j], 1);
            s1v[j] += __shfl_xor_sync(0xffffffffu, s1v[j], 2);
            s1v[j] += __shfl_xor_sync(0xffffffffu, s1v[j], 4);
            s2v[j] += __shfl_xor_sync(0xffffffffu, s2v[j], 1);
            s2v[j] += __shfl_xor_sync(0xffffffffu, s2v[j], 2);
            s2v[j] += __shfl_xor_sync(0xffffffffu, s2v[j], 4);
        }
        if (c4 == 0) {
#pragma unroll
            for (int j = 0; j < 8; j++) {
                st_s1[16 * j + g] = s1v[j];
                st_s2[16 * j + g] = s2v[j];
            }
        }
        barsync(10, 128);      // producers-only: stats visible

        // ---- tail staging: last 152 cols of each of 128 rows into stage smem ----
        float* tail = (float*)smem;                    // [128][153]
        for (int idx = p; idx < MTILE * 38; idx += 128) {
            int r = idx / 38, q = (idx % 38) * 4;
            float4 v = *(const float4*)(x + (size_t)(row0 + r) * L + (L - 152) + q);
            float* tp = tail + r * 153;
            tp[q] = v.x; tp[q + 1] = v.y; tp[q + 2] = v.z; tp[q + 3] = v.w;
        }
        barsync(10, 128);      // producers-only: tail visible

        // ---- AR2 fit + std bounds: thread p handles row p ----
        {
            const float* y = tail + p * 153 + 2;       // y[0..149] = x[-150:]
            float A11 = 0.f, A22 = 0.f, A12 = 0.f, b1 = 0.f, b2 = 0.f;
            float ym2 = y[0], ym1 = y[1];
#pragma unroll 4
            for (int j2 = 2; j2 < 150; j2++) {
                float yc = y[j2];
                A22 = fmaf(ym2, ym2, A22);
                A11 = fmaf(ym1, ym1, A11);
                A12 = fmaf(ym1, ym2, A12);
                b1  = fmaf(ym1, yc, b1);
                b2  = fmaf(ym2, yc, b2);
                ym2 = ym1; ym1 = yc;
            }
            A11 += 0.001f; A22 += 0.001f;
            float det = A11 * A22 - A12 * A12;
            float inv = 1.0f / det;
            float a1c = (b1 * A22 - b2 * A12) * inv;
            float a2c = (A11 * b2 - A12 * b1) * inv;

            float s1r = st_s1[p], s2r = st_s2[p];
            float mean = s1r * (1.0f / 2048.0f);
            float var  = fmaxf((s2r - s1r * mean) * (1.0f / 2047.0f), 0.f);
            float hstd = fmaxf(sqrtf(var), 1e-6f);
            float last = y[149];

            rp_a1[p] = a1c; rp_a2[p] = a2c;
            rp_y1[p] = y[149]; rp_y2[p] = y[148];
            rp_lo[p] = last - 4.0f * hstd;
            rp_hi[p] = last + 4.0f * hstd;
        }
        asm volatile("membar.cta;" ::: "memory");
        bararrive(9, TPB);     // release consumers into epilogue
    }
}

extern "C" void kernel_launch(void* const* d_in, const int* in_sizes, int n_in,
                              void* d_out, int out_size)
{
    const float* x = (const float*)d_in[0];
    const float* W = (const float*)d_in[1];
    if (n_in >= 2 && in_sizes[0] < in_sizes[1]) {   // defensive: x is the big tensor
        const float* t = x; x = W; W = t;
    }
    float* out = (float*)d_out;

    cudaFuncSetAttribute(ar2_ws_kernel,
                         cudaFuncAttributeMaxDynamicSharedMemorySize, SMEM_DYN);

    prep_W_kernel<<<L / 32, 256>>>(W);                            // 64 blocks
    ar2_ws_kernel<<<(32 * 512) / MTILE, TPB, SMEM_DYN>>>(x, out); // 128 blocks
}